// round 1
// baseline (speedup 1.0000x reference)
#include <cuda_runtime.h>
#include <cstdint>

#define SEQ     512
#define INP     5
#define HID     64
#define TB      32        // batch rows per CTA
#define PAD     68        // padded row length (floats) for W_hh / h in smem
#define THREADS 256

// ---------------------------------------------------------------------------
// packed f32x2 helpers (Blackwell native paired fp32 math)
// ---------------------------------------------------------------------------
__device__ __forceinline__ void fma2(unsigned long long& d,
                                     unsigned long long a,
                                     unsigned long long b) {
    asm("fma.rn.f32x2 %0, %1, %2, %0;" : "+l"(d) : "l"(a), "l"(b));
}
__device__ __forceinline__ float2 unpack2(unsigned long long v) {
    float lo, hi;
    asm("mov.b64 {%0, %1}, %2;" : "=f"(lo), "=f"(hi) : "l"(v));
    return make_float2(lo, hi);
}

__device__ __forceinline__ float sigmoid_f(float x) {
    return __fdividef(1.f, 1.f + __expf(-x));
}
__device__ __forceinline__ float tanh_f(float x) {
    // 2*sigmoid(2x) - 1 ; correct saturation at +/-inf
    return __fdividef(2.f, 1.f + __expf(-2.f * x)) - 1.f;
}

// ---------------------------------------------------------------------------
// One CTA owns TB=32 batch rows for the whole 512-step recurrence.
// Thread t: j = t & 63 (hidden index), bg = t >> 6 (batch octet).
// Each thread computes all 4 gates for (8 batch rows, hidden j), so the
// c/h update is register-local. h double-buffered in smem (1 bar/step).
// ---------------------------------------------------------------------------
__global__ void __launch_bounds__(THREADS, 2)
lstm_kernel(const float* __restrict__ inputs,  // [B, SEQ, INP]
            const float* __restrict__ W_ih,    // [256, INP]
            const float* __restrict__ W_hh,    // [256, HID]
            const float* __restrict__ b_ih,    // [256]
            const float* __restrict__ b_hh,    // [256]
            const float* __restrict__ fc_w,    // [1, HID]
            const float* __restrict__ fc_b,    // [1]
            float* __restrict__ out)           // [B, 1]
{
    extern __shared__ float sm[];
    float* Wsh = sm;                    // 256*PAD floats (W_hh, row-padded)
    float* Hsh = Wsh + 256 * PAD;       // 2 * TB*PAD floats (h double buffer)
    float* Xsh = Hsh + 2 * TB * PAD;    // 2 * TB*INP floats (x double buffer)

    const int t      = threadIdx.x;
    const int j      = t & 63;
    const int bg     = t >> 6;          // 0..3 -> batch rows bg*8 .. bg*8+7
    const int batch0 = blockIdx.x * TB;

    // Stage W_hh into padded smem (row r at Wsh + r*PAD)
    for (int idx = t; idx < 256 * HID; idx += THREADS) {
        int r = idx >> 6, k = idx & 63;
        Wsh[r * PAD + k] = W_hh[idx];
    }
    // h0 = 0 (buffer 0)
    for (int idx = t; idx < TB * PAD; idx += THREADS) Hsh[idx] = 0.f;
    // Prefetch x for step 0 into x-buffer 0
    for (int idx = t; idx < TB * INP; idx += THREADS) {
        int b = idx / INP, i = idx - b * INP;
        Xsh[idx] = inputs[(size_t)(batch0 + b) * (SEQ * INP) + i];
    }

    // Per-thread constants: W_ih rows + combined bias for (gate g, hidden j)
    float wih[4][INP], bias[4];
#pragma unroll
    for (int g = 0; g < 4; ++g) {
        int r = g * HID + j;
#pragma unroll
        for (int i = 0; i < INP; ++i) wih[g][i] = W_ih[r * INP + i];
        bias[g] = b_ih[r] + b_hh[r];
    }

    float c[8];
#pragma unroll
    for (int b = 0; b < 8; ++b) c[b] = 0.f;

    __syncthreads();

    const ulonglong2* W0 = (const ulonglong2*)(Wsh + (0 * HID + j) * PAD);
    const ulonglong2* W1 = (const ulonglong2*)(Wsh + (1 * HID + j) * PAD);
    const ulonglong2* W2 = (const ulonglong2*)(Wsh + (2 * HID + j) * PAD);
    const ulonglong2* W3 = (const ulonglong2*)(Wsh + (3 * HID + j) * PAD);

    for (int s = 0; s < SEQ; ++s) {
        const float* hin  = Hsh + (s & 1) * (TB * PAD);
        float*       hout = Hsh + ((s + 1) & 1) * (TB * PAD);
        const float* xin  = Xsh + (s & 1) * (TB * INP);
        float*       xnx  = Xsh + ((s + 1) & 1) * (TB * INP);

        // Prefetch next step's inputs (hidden under this step's compute)
        if (s + 1 < SEQ) {
            for (int idx = t; idx < TB * INP; idx += THREADS) {
                int b = idx / INP, i = idx - b * INP;
                xnx[idx] = inputs[(size_t)(batch0 + b) * (SEQ * INP)
                                  + (size_t)(s + 1) * INP + i];
            }
        }

        // gates[b][g] = sum_k W_hh[g*64+j][k] * h[b][k]   (packed f32x2)
        unsigned long long acc[8][4];
#pragma unroll
        for (int b = 0; b < 8; ++b)
#pragma unroll
            for (int g = 0; g < 4; ++g) acc[b][g] = 0ull;

        const float* hb = hin + bg * 8 * PAD;
#pragma unroll
        for (int k4 = 0; k4 < 16; ++k4) {
            ulonglong2 w0 = W0[k4], w1 = W1[k4], w2 = W2[k4], w3 = W3[k4];
#pragma unroll
            for (int b = 0; b < 8; ++b) {
                ulonglong2 h = ((const ulonglong2*)(hb + b * PAD))[k4];
                fma2(acc[b][0], w0.x, h.x); fma2(acc[b][0], w0.y, h.y);
                fma2(acc[b][1], w1.x, h.x); fma2(acc[b][1], w1.y, h.y);
                fma2(acc[b][2], w2.x, h.x); fma2(acc[b][2], w2.y, h.y);
                fma2(acc[b][3], w3.x, h.x); fma2(acc[b][3], w3.y, h.y);
            }
        }

        // Epilogue: add x-projection + biases, activations, c/h update
#pragma unroll
        for (int b = 0; b < 8; ++b) {
            int bb = bg * 8 + b;
            float x0 = xin[bb * INP + 0], x1 = xin[bb * INP + 1],
                  x2 = xin[bb * INP + 2], x3 = xin[bb * INP + 3],
                  x4 = xin[bb * INP + 4];
            float gate[4];
#pragma unroll
            for (int g = 0; g < 4; ++g) {
                float2 p = unpack2(acc[b][g]);
                gate[g] = p.x + p.y + bias[g]
                        + x0 * wih[g][0] + x1 * wih[g][1] + x2 * wih[g][2]
                        + x3 * wih[g][3] + x4 * wih[g][4];
            }
            float ig = sigmoid_f(gate[0]);
            float fg = sigmoid_f(gate[1]);
            float gg = tanh_f(gate[2]);
            float og = sigmoid_f(gate[3]);
            float cn = fg * c[b] + ig * gg;
            c[b] = cn;
            hout[bb * PAD + j] = og * tanh_f(cn);
        }
        __syncthreads();
    }

    // Final FC + leaky ReLU. Last write was into buffer (SEQ & 1) == 0.
    const float* hf   = Hsh;
    const int    w    = t >> 5;
    const int    lane = t & 31;
    const float  fw0  = fc_w[lane];
    const float  fw1  = fc_w[lane + 32];
    const float  fb   = fc_b[0];
#pragma unroll
    for (int q = 0; q < 4; ++q) {
        int   b = w * 4 + q;
        float p = hf[b * PAD + lane] * fw0 + hf[b * PAD + lane + 32] * fw1;
#pragma unroll
        for (int off = 16; off > 0; off >>= 1)
            p += __shfl_xor_sync(0xffffffffu, p, off);
        if (lane == 0) {
            float v = p + fb;
            out[batch0 + b] = (v >= 0.f) ? v : 0.01f * v;
        }
    }
}

extern "C" void kernel_launch(void* const* d_in, const int* in_sizes, int n_in,
                              void* d_out, int out_size) {
    const float* inputs = (const float*)d_in[0];
    const float* W_ih   = (const float*)d_in[1];
    const float* W_hh   = (const float*)d_in[2];
    const float* b_ih   = (const float*)d_in[3];
    const float* b_hh   = (const float*)d_in[4];
    const float* fc_w   = (const float*)d_in[5];
    const float* fc_b   = (const float*)d_in[6];
    float*       out    = (float*)d_out;

    const int batch = in_sizes[0] / (SEQ * INP);   // 8192
    const int smem  = (256 * PAD + 2 * TB * PAD + 2 * TB * INP) * (int)sizeof(float); // 88320 B

    cudaFuncSetAttribute(lstm_kernel,
                         cudaFuncAttributeMaxDynamicSharedMemorySize, smem);
    lstm_kernel<<<batch / TB, THREADS, smem>>>(inputs, W_ih, W_hh, b_ih, b_hh,
                                               fc_w, fc_b, out);
}

// round 2
// speedup vs baseline: 1.2181x; 1.2181x over previous
#include <cuda_runtime.h>
#include <cstdint>

#define SEQ     512
#define INP     5
#define HID     64
#define RPP     7                 // batch rows per warp-pair
#define PAIRS   8                 // warp-pairs per CTA
#define TB      (RPP * PAIRS)     // 56 batch rows per CTA
#define PAD     68                // padded row length (floats), conflict-free
#define THREADS 512
#define PSZ     1024              // floats per pair region: 2*7*68 h + 2*36 x

// packed f32x2 helpers (Blackwell native paired fp32 math)
__device__ __forceinline__ void fma2(unsigned long long& d,
                                     unsigned long long a,
                                     unsigned long long b) {
    asm("fma.rn.f32x2 %0, %1, %2, %0;" : "+l"(d) : "l"(a), "l"(b));
}
__device__ __forceinline__ float2 unpack2(unsigned long long v) {
    float lo, hi;
    asm("mov.b64 {%0, %1}, %2;" : "=f"(lo), "=f"(hi) : "l"(v));
    return make_float2(lo, hi);
}

__device__ __forceinline__ float sigmoid_f(float x) {
    return __fdividef(1.f, 1.f + __expf(-x));
}
__device__ __forceinline__ float tanh_f(float x) {
    return __fdividef(2.f, 1.f + __expf(-2.f * x)) - 1.f;
}

// ---------------------------------------------------------------------------
// One CTA = 512 threads = 8 independent warp-PAIRS. Each pair owns RPP=7
// batch rows for the whole recurrence. Within a pair, thread (lane, half)
// owns hidden index j = lane + 32*half and computes all 4 gates for all 7
// rows -> c/h update register-local. Pairs sync only among their own 64
// threads via named barriers, so pairs drift out of phase and one pair's
// MUFU epilogue overlaps another pair's FMA matmul.
// ---------------------------------------------------------------------------
__global__ void __launch_bounds__(THREADS, 1)
lstm_kernel(const float* __restrict__ inputs,  // [B, SEQ, INP]
            const float* __restrict__ W_ih,    // [256, INP]
            const float* __restrict__ W_hh,    // [256, HID]
            const float* __restrict__ b_ih,    // [256]
            const float* __restrict__ b_hh,    // [256]
            const float* __restrict__ fc_w,    // [1, HID]
            const float* __restrict__ fc_b,    // [1]
            float* __restrict__ out,           // [B, 1]
            int batch)
{
    extern __shared__ float sm[];
    float* Wsh = sm;                                   // 256*PAD floats

    const int t    = threadIdx.x;
    const int lane = t & 31;
    const int warp = t >> 5;
    const int pair = warp >> 1;                        // 0..7
    const int half = warp & 1;
    const int j    = lane + (half << 5);               // 0..63 within pair

    float* Hp = Wsh + 256 * PAD + pair * PSZ;          // 2 x (RPP*PAD) h bufs
    float* Xp = Hp + 2 * RPP * PAD;                    // 2 x 36 x bufs

    const int rowbase = blockIdx.x * TB + pair * RPP;

    // Stage W_hh into padded smem (all 512 threads)
    for (int idx = t; idx < 256 * HID; idx += THREADS) {
        int r = idx >> 6, k = idx & 63;
        Wsh[r * PAD + k] = W_hh[idx];
    }
    // h0 = 0 (buffer 0) for this pair
    for (int idx = j; idx < RPP * PAD; idx += 64) Hp[idx] = 0.f;
    // Prefetch x for step 0 into x-buffer 0
    if (j < RPP * INP) {
        int b = j / INP, i = j - b * INP;
        int row = min(rowbase + b, batch - 1);
        Xp[b * INP + i] = inputs[(size_t)row * (SEQ * INP) + i];
    }

    // Per-thread constants: W_ih rows + combined bias for (gate g, hidden j)
    float wih[4][INP], bias[4];
#pragma unroll
    for (int g = 0; g < 4; ++g) {
        int r = g * HID + j;
#pragma unroll
        for (int i = 0; i < INP; ++i) wih[g][i] = W_ih[r * INP + i];
        bias[g] = b_ih[r] + b_hh[r];
    }

    float c[RPP];
#pragma unroll
    for (int b = 0; b < RPP; ++b) c[b] = 0.f;

    __syncthreads();   // W + all pair buffers staged

    const float* Wj = Wsh + j * PAD;    // gate g row at + g*HID*PAD

    for (int s = 0; s < SEQ; ++s) {
        const float* hin  = Hp + (s & 1) * (RPP * PAD);
        float*       hout = Hp + ((s + 1) & 1) * (RPP * PAD);
        const float* xin  = Xp + (s & 1) * 36;
        float*       xnx  = Xp + ((s + 1) & 1) * 36;

        // Prefetch next step's inputs for this pair (35 scalars, 64 threads)
        if (s + 1 < SEQ && j < RPP * INP) {
            int b = j / INP, i = j - b * INP;
            int row = min(rowbase + b, batch - 1);
            xnx[b * INP + i] = inputs[(size_t)row * (SEQ * INP)
                                      + (size_t)(s + 1) * INP + i];
        }

        // gates[b][g] = sum_k W_hh[g*64+j][k] * h[b][k]   (packed f32x2)
        unsigned long long acc[RPP][4];
#pragma unroll
        for (int b = 0; b < RPP; ++b)
#pragma unroll
            for (int g = 0; g < 4; ++g) acc[b][g] = 0ull;

#pragma unroll
        for (int k4 = 0; k4 < 16; ++k4) {
            ulonglong2 w0 = ((const ulonglong2*)(Wj + 0 * HID * PAD))[k4];
            ulonglong2 w1 = ((const ulonglong2*)(Wj + 1 * HID * PAD))[k4];
            ulonglong2 w2 = ((const ulonglong2*)(Wj + 2 * HID * PAD))[k4];
            ulonglong2 w3 = ((const ulonglong2*)(Wj + 3 * HID * PAD))[k4];
#pragma unroll
            for (int b = 0; b < RPP; ++b) {
                ulonglong2 h = ((const ulonglong2*)(hin + b * PAD))[k4];
                fma2(acc[b][0], w0.x, h.x); fma2(acc[b][0], w0.y, h.y);
                fma2(acc[b][1], w1.x, h.x); fma2(acc[b][1], w1.y, h.y);
                fma2(acc[b][2], w2.x, h.x); fma2(acc[b][2], w2.y, h.y);
                fma2(acc[b][3], w3.x, h.x); fma2(acc[b][3], w3.y, h.y);
            }
        }

        // Epilogue: x-projection + biases, activations, c/h update
#pragma unroll
        for (int b = 0; b < RPP; ++b) {
            float x0 = xin[b * INP + 0], x1 = xin[b * INP + 1],
                  x2 = xin[b * INP + 2], x3 = xin[b * INP + 3],
                  x4 = xin[b * INP + 4];
            float gate[4];
#pragma unroll
            for (int g = 0; g < 4; ++g) {
                float2 p = unpack2(acc[b][g]);
                gate[g] = p.x + p.y + bias[g]
                        + x0 * wih[g][0] + x1 * wih[g][1] + x2 * wih[g][2]
                        + x3 * wih[g][3] + x4 * wih[g][4];
            }
            float ig = sigmoid_f(gate[0]);
            float fg = sigmoid_f(gate[1]);
            float gg = tanh_f(gate[2]);
            float og = sigmoid_f(gate[3]);
            float cn = fg * c[b] + ig * gg;
            c[b] = cn;
            hout[b * PAD + j] = og * tanh_f(cn);
        }

        // Pair-local sync: only the 64 threads sharing these batch rows
        asm volatile("bar.sync %0, 64;" :: "r"(pair) : "memory");
    }

    // Final FC + leaky ReLU. Last write was into buffer (SEQ & 1) == 0.
    const float* hf  = Hp;
    const float  fw0 = fc_w[lane];
    const float  fw1 = fc_w[lane + 32];
    const float  fb  = fc_b[0];
    const int    b0  = half ? 4 : 0;
    const int    b1  = half ? RPP : 4;
    for (int b = b0; b < b1; ++b) {
        float p = hf[b * PAD + lane] * fw0 + hf[b * PAD + lane + 32] * fw1;
#pragma unroll
        for (int off = 16; off > 0; off >>= 1)
            p += __shfl_xor_sync(0xffffffffu, p, off);
        if (lane == 0) {
            int row = rowbase + b;
            if (row < batch) {
                float v = p + fb;
                out[row] = (v >= 0.f) ? v : 0.01f * v;
            }
        }
    }
}

extern "C" void kernel_launch(void* const* d_in, const int* in_sizes, int n_in,
                              void* d_out, int out_size) {
    const float* inputs = (const float*)d_in[0];
    const float* W_ih   = (const float*)d_in[1];
    const float* W_hh   = (const float*)d_in[2];
    const float* b_ih   = (const float*)d_in[3];
    const float* b_hh   = (const float*)d_in[4];
    const float* fc_w   = (const float*)d_in[5];
    const float* fc_b   = (const float*)d_in[6];
    float*       out    = (float*)d_out;

    const int batch = in_sizes[0] / (SEQ * INP);                 // 8192
    const int grid  = (batch + TB - 1) / TB;                     // 147
    const int smem  = (256 * PAD + PAIRS * PSZ) * (int)sizeof(float); // 102400 B

    cudaFuncSetAttribute(lstm_kernel,
                         cudaFuncAttributeMaxDynamicSharedMemorySize, smem);
    lstm_kernel<<<grid, THREADS, smem>>>(inputs, W_ih, W_hh, b_ih, b_hh,
                                         fc_w, fc_b, out, batch);
}